// round 16
// baseline (speedup 1.0000x reference)
#include <cuda_runtime.h>
#include <cuda_bf16.h>

// Problem constants
#define NTOK   4096      // B*S
#define DIN    2048
#define DOUT   2048
#define NEXP   16
#define RANK   16
#define TOPK   2
#define NASSIGN (NTOK*TOPK)   // 8192
#define ALPHA  2.0f
#define DSPLIT 8              // phase-A d-reduction split (4 chunks of 64 per block)
#define TILE_A 64             // phase-A tokens per tile
#define SPT_A  8              // phase-A tile slots per expert (capacity 512)
#define TILE_T 128            // phase-B tile granularity
#define TPE    4              // phase-B tile slots per expert
#define WIN    64             // phase-B token window per block
#define GRP    4              // phase-B inner group

#define A_BUF_FLOATS (TILE_A * 68 + 16 * 68)         // sx + sw per stage buffer
#define A_SMEM_BYTES (2 * A_BUF_FLOATS * 4)          // 43520 B dynamic -> 5 blocks/SM

typedef unsigned long long ull;

// ---------------- packed f32x2 helpers (FFMA2 via PTX) ----------------
__device__ __forceinline__ void fma2(ull &acc, ull a, ull b) {
    asm("fma.rn.f32x2 %0, %1, %2, %0;" : "+l"(acc) : "l"(a), "l"(b));
}
__device__ __forceinline__ ull add2(ull a, ull b) {
    ull r; asm("add.rn.f32x2 %0, %1, %2;" : "=l"(r) : "l"(a), "l"(b)); return r;
}
__device__ __forceinline__ float hadd2(ull v) {
    float lo, hi; asm("mov.b64 {%0,%1}, %2;" : "=f"(lo), "=f"(hi) : "l"(v));
    return lo + hi;
}
__device__ __forceinline__ void cp16(void* smem, const void* gmem) {
    unsigned sa = (unsigned)__cvta_generic_to_shared(smem);
    asm volatile("cp.async.cg.shared.global [%0], [%1], 16;" :: "r"(sa), "l"(gmem));
}
#define CP_COMMIT()  asm volatile("cp.async.commit_group;")
#define CP_WAIT(n)   asm volatile("cp.async.wait_group %0;" :: "n"(n))
__device__ __forceinline__ void red_v2(float* p, float a, float b) {
    asm volatile("red.global.add.v2.f32 [%0], {%1, %2};" :: "l"(p), "f"(a), "f"(b) : "memory");
}

// ---------------- device scratch ----------------
__device__ int   d_run[32];                  // per-(k,e) counters (memset to 0 each run)
__device__ int   d_list[2][NEXP * NTOK];     // bucketed token ids: [k][e*NTOK + pos]
__device__ float d_part[DSPLIT][NASSIGN * RANK];  // phase-A partial dots

// ---------------- kernel 1: hierarchical scatter (frozen, best measured) ----------------
__global__ __launch_bounds__(256) void scatter_kernel(const int* __restrict__ idxs) {
    __shared__ int s_hist[32], s_run[32];
    int tid = threadIdx.x;
    int i = blockIdx.x * 256 + tid;          // 0..NASSIGN-1
    int k = i & 1, t = i >> 1;
    int e = idxs[i] & 15;
    int c = k * 16 + e;

    if (tid < 32) s_hist[tid] = 0;
    __syncthreads();
    atomicAdd(&s_hist[c], 1);
    __syncthreads();
    if (tid < 32) {
        int base = s_hist[tid] ? atomicAdd(&d_run[tid], s_hist[tid]) : 0;
        s_run[tid] = base;
    }
    __syncthreads();
    int pos = atomicAdd(&s_run[c], 1);       // global bucket position
    d_list[k][e * NTOK + pos] = t;
}

// ---------------- kernel 2: phase A — 64-token tiles, 5 blocks/SM, cp.async pipelined ----------------
// grid (NEXP*SPT_A, 2, DSPLIT), block 256: thread (j = tid>>2, rq = tid&3) -> token j, ranks {4i+rq}.
__global__ __launch_bounds__(256) void phaseA_kernel(const float* __restrict__ x,
                                                     const float* __restrict__ w_a,
                                                     float* __restrict__ out) {
    int tid = threadIdx.x;

    // zero this block's slice of out (8M floats / 2048 blocks = 4096 floats), BEFORE early return
    {
        int bid = blockIdx.x + (NEXP * SPT_A) * (blockIdx.y + 2 * blockIdx.z);  // 0..2047
        float4* oz = (float4*)out + (size_t)bid * 1024;
        float4 z = make_float4(0.f, 0.f, 0.f, 0.f);
#pragma unroll
        for (int i = 0; i < 4; i++) oz[i * 256 + tid] = z;
    }

    int k   = blockIdx.y;
    int e   = blockIdx.x >> 3;     // expert
    int sub = blockIdx.x & 7;      // 64-token slot within expert
    int cnt = d_run[k * 16 + e];
    int t0i = sub * TILE_A;
    int cl  = cnt - t0i;
    if (cl <= 0) return;
    if (cl > TILE_A) cl = TILE_A;
    int start = e * NTOK + t0i;
    int ds = blockIdx.z;

    extern __shared__ float dyn[];           // 2 x (sx[64*68] + sw[16*68])
    __shared__ int s_tok[TILE_A];

    int j  = tid >> 2;         // token slot 0..63
    int rq = tid & 3;          // rank class: handles ranks {4i+rq}

    if (tid < TILE_A) {
        int jcl = tid < cl ? tid : (cl - 1);
        s_tok[tid] = d_list[k][start + jcl];
    }
    __syncthreads();

    const float* wa_e = w_a + (size_t)e * RANK * DIN;
    int dbase0 = ds * (DIN / DSPLIT);        // 256-wide slice, 4 chunks of 64

    auto stage = [&](int buf, int ch) {
        float* sxb = dyn + buf * A_BUF_FLOATS;
        float* swb = sxb + TILE_A * 68;
        int db = dbase0 + ch * 64;
#pragma unroll
        for (int it = 0; it < 4; it++) {
            int l = it * 256 + tid;          // 1024 f4 = 64 tok x 16
            int tok = l >> 4, c4 = l & 15;
            cp16(sxb + tok * 68 + c4 * 4,
                 x + (size_t)s_tok[tok] * DIN + db + c4 * 4);
        }
        {
            int r = tid >> 4, c4 = tid & 15; // 256 f4 = 16 rows x 16
            cp16(swb + r * 68 + c4 * 4,
                 wa_e + (size_t)r * DIN + db + c4 * 4);
        }
        CP_COMMIT();
    };

    ull acc[4];
#pragma unroll
    for (int i = 0; i < 4; i++) acc[i] = 0ull;

    stage(0, 0);
    int buf = 0;
#pragma unroll
    for (int ch = 0; ch < 4; ch++) {
        if (ch < 3) { stage(buf ^ 1, ch + 1); CP_WAIT(1); }
        else        { CP_WAIT(0); }
        __syncthreads();

        const float* sxb = dyn + buf * A_BUF_FLOATS;
        const float* swb = sxb + TILE_A * 68;
        const float* sxr = sxb + j * 68;
        const float* swr = swb + rq * 68;    // ranks 4i+rq at rows (4i+rq)*68
#pragma unroll
        for (int c4 = 0; c4 < 16; c4++) {
            ulonglong2 xv = *(const ulonglong2*)(sxr + c4 * 4);
#pragma unroll
            for (int i = 0; i < 4; i++) {
                ulonglong2 wv = *(const ulonglong2*)(swr + (4 * i) * 68 + c4 * 4);
                fma2(acc[i], xv.x, wv.x);
                fma2(acc[i], xv.y, wv.y);
            }
        }
        __syncthreads();
        buf ^= 1;
    }

    if (j < cl) {
        int a = s_tok[j] * 2 + k;
        float* p = &d_part[ds][(size_t)a * RANK];
#pragma unroll
        for (int i = 0; i < 4; i++) p[4 * i + rq] = hadd2(acc[i]);
    }
}

// ---------------- kernel 3: phase B — 2 consecutive d/thread, 256 threads, red_v2 (frozen) ----------------
// grid (NEXP*TPE, DOUT/512, 4), block 256. z = (zslice<<1)|k.
__global__ __launch_bounds__(256) void phaseB_kernel(const float* __restrict__ w_b,
                                                     const float* __restrict__ routing,
                                                     float* __restrict__ out) {
    int kk = blockIdx.z & 1;
    int zs = blockIdx.z >> 1;
    int ti = blockIdx.x;
    int e   = ti >> 2;
    int sub = ti & 3;
    int cnt = d_run[kk * 16 + e];
    int t0i = sub * TILE_T + zs * WIN;
    int cl  = cnt - t0i;
    if (cl <= 0) return;
    if (cl > WIN) cl = WIN;
    int start = e * NTOK + t0i;

    __shared__ float sg[WIN * 16];
    __shared__ int   s_tok[WIN];

    int tid = threadIdx.x;
    if (tid < WIN) {
        int jcl = tid < cl ? tid : (cl - 1);
        s_tok[tid] = d_list[kk][start + jcl];
    }
    {   // stage g with fused DSPLIT-combine + silu*routing*alpha: 64 tok x 4 quads
        int j = tid >> 2, q = tid & 3;
        int jcl = j < cl ? j : (cl - 1);
        int t = d_list[kk][start + jcl];
        int a = t * 2 + kk;
        size_t off = (size_t)a * RANK + q * 4;
        float4 s = *(const float4*)(&d_part[0][off]);
#pragma unroll
        for (int ds = 1; ds < DSPLIT; ds++) {
            float4 p = *(const float4*)(&d_part[ds][off]);
            s.x += p.x; s.y += p.y; s.z += p.z; s.w += p.w;
        }
        float rs = routing[a] * ALPHA;
        float4 g;
        g.x = rs * s.x * (1.0f / (1.0f + __expf(-s.x)));
        g.y = rs * s.y * (1.0f / (1.0f + __expf(-s.y)));
        g.z = rs * s.z * (1.0f / (1.0f + __expf(-s.z)));
        g.w = rs * s.w * (1.0f / (1.0f + __expf(-s.w)));
        *(float4*)(sg + j * 16 + q * 4) = g;
    }
    __syncthreads();

    int d0 = blockIdx.y * 512 + tid * 2;     // 2 consecutive outputs per thread
    const ulonglong2* wbp0 = (const ulonglong2*)(w_b + ((size_t)e * DOUT + d0) * RANK);
    const ulonglong2* wbp1 = (const ulonglong2*)(w_b + ((size_t)e * DOUT + d0 + 1) * RANK);
    ulonglong2 p0 = wbp0[0], p1 = wbp0[1], p2 = wbp0[2], p3 = wbp0[3];
    ulonglong2 q0 = wbp1[0], q1 = wbp1[1], q2 = wbp1[2], q3 = wbp1[3];

    for (int j0 = 0; j0 < cl; j0 += GRP) {
        float r0[GRP], r1[GRP];
#pragma unroll
        for (int u = 0; u < GRP; u++) {
            int jj = j0 + u; if (jj >= cl) jj = cl - 1;
            const ulonglong2* g = (const ulonglong2*)(sg + jj * 16);
            ulonglong2 ga = g[0], gb = g[1], gc = g[2], gd = g[3];
            ull a0 = 0ull, a1 = 0ull, b0 = 0ull, b1 = 0ull;
            fma2(a0, ga.x, p0.x); fma2(a1, ga.y, p0.y);
            fma2(b0, ga.x, q0.x); fma2(b1, ga.y, q0.y);
            fma2(a0, gb.x, p1.x); fma2(a1, gb.y, p1.y);
            fma2(b0, gb.x, q1.x); fma2(b1, gb.y, q1.y);
            fma2(a0, gc.x, p2.x); fma2(a1, gc.y, p2.y);
            fma2(b0, gc.x, q2.x); fma2(b1, gc.y, q2.y);
            fma2(a0, gd.x, p3.x); fma2(a1, gd.y, p3.y);
            fma2(b0, gd.x, q3.x); fma2(b1, gd.y, q3.y);
            r0[u] = hadd2(add2(a0, a1));
            r1[u] = hadd2(add2(b0, b1));
        }
#pragma unroll
        for (int u = 0; u < GRP; u++) {
            int jj = j0 + u;
            if (jj < cl) {
                red_v2(out + (size_t)s_tok[jj] * DOUT + d0, r0[u], r1[u]);
            }
        }
    }
}

// ---------------- launcher ----------------
extern "C" void kernel_launch(void* const* d_in, const int* in_sizes, int n_in,
                              void* d_out, int out_size) {
    const float* x       = (const float*)d_in[0];
    const float* routing = (const float*)d_in[1];
    const int*   idxs    = (const int*)d_in[2];   // int32 (JAX x64 disabled)
    const float* w_a     = (const float*)d_in[3];
    const float* w_b     = (const float*)d_in[4];
    float*       out     = (float*)d_out;

    cudaFuncSetAttribute(phaseA_kernel, cudaFuncAttributeMaxDynamicSharedMemorySize,
                         A_SMEM_BYTES);
    void* run_ptr = nullptr;
    cudaGetSymbolAddress(&run_ptr, d_run);

    cudaMemsetAsync(run_ptr, 0, 32 * sizeof(int));
    scatter_kernel<<<NASSIGN / 256, 256>>>(idxs);
    phaseA_kernel<<<dim3(NEXP * SPT_A, 2, DSPLIT), 256, A_SMEM_BYTES>>>(x, w_a, out);
    phaseB_kernel<<<dim3(NEXP * TPE, DOUT / 512, 4), 256>>>(w_b, routing, out);
}

// round 17
// speedup vs baseline: 1.1760x; 1.1760x over previous
#include <cuda_runtime.h>
#include <cuda_bf16.h>

// Problem constants
#define NTOK   4096      // B*S
#define DIN    2048
#define DOUT   2048
#define NEXP   16
#define RANK   16
#define TOPK   2
#define NASSIGN (NTOK*TOPK)   // 8192
#define ALPHA  2.0f
#define DSPLIT 8              // phase-A d-reduction split (4 chunks of 64 per block)
#define TILE_T 128            // tokens per tile
#define TPE    4              // static tile slots per expert (capacity 512 tokens)
#define WIN    64             // phase-B token window per block
#define GRP    4              // phase-B inner group

#define A_BUF_FLOATS (128 * 68 + 16 * 68)            // sx + sw per stage buffer
#define A_SMEM_BYTES (2 * A_BUF_FLOATS * 4)          // 78336 B dynamic

typedef unsigned long long ull;

// ---------------- packed f32x2 helpers (FFMA2 via PTX) ----------------
__device__ __forceinline__ void fma2(ull &acc, ull a, ull b) {
    asm("fma.rn.f32x2 %0, %1, %2, %0;" : "+l"(acc) : "l"(a), "l"(b));
}
__device__ __forceinline__ ull add2(ull a, ull b) {
    ull r; asm("add.rn.f32x2 %0, %1, %2;" : "=l"(r) : "l"(a), "l"(b)); return r;
}
__device__ __forceinline__ float hadd2(ull v) {
    float lo, hi; asm("mov.b64 {%0,%1}, %2;" : "=f"(lo), "=f"(hi) : "l"(v));
    return lo + hi;
}
__device__ __forceinline__ void cp16(void* smem, const void* gmem) {
    unsigned sa = (unsigned)__cvta_generic_to_shared(smem);
    asm volatile("cp.async.cg.shared.global [%0], [%1], 16;" :: "r"(sa), "l"(gmem));
}
#define CP_COMMIT()  asm volatile("cp.async.commit_group;")
#define CP_WAIT(n)   asm volatile("cp.async.wait_group %0;" :: "n"(n))
__device__ __forceinline__ void red_v2(float* p, float a, float b) {
    asm volatile("red.global.add.v2.f32 [%0], {%1, %2};" :: "l"(p), "f"(a), "f"(b) : "memory");
}

// ---------------- device scratch ----------------
__device__ int   d_run[32];                  // per-(k,e) counters (zeroed by zero_run_kernel of PREVIOUS call; static-zero initially)
__device__ int   d_list[2][NEXP * NTOK];     // bucketed token ids: [k][e*NTOK + pos]
__device__ float d_part[DSPLIT][NASSIGN * RANK];  // phase-A partial dots

// ---------------- kernel 1: hierarchical scatter (frozen, best measured) ----------------
__global__ __launch_bounds__(256) void scatter_kernel(const int* __restrict__ idxs) {
    __shared__ int s_hist[32], s_run[32];
    int tid = threadIdx.x;
    int i = blockIdx.x * 256 + tid;          // 0..NASSIGN-1
    int k = i & 1, t = i >> 1;
    int e = idxs[i] & 15;
    int c = k * 16 + e;

    if (tid < 32) s_hist[tid] = 0;
    __syncthreads();
    atomicAdd(&s_hist[c], 1);
    __syncthreads();
    if (tid < 32) {
        int base = s_hist[tid] ? atomicAdd(&d_run[tid], s_hist[tid]) : 0;
        s_run[tid] = base;
    }
    __syncthreads();
    int pos = atomicAdd(&s_run[c], 1);       // global bucket position
    d_list[k][e * NTOK + pos] = t;
}

// ---------------- kernel 2: phase A — R14 config (measured best) ----------------
// grid (NEXP*TPE, 2, DSPLIT), block 256: 2 threads/token, rh = odd/even ranks.
__global__ __launch_bounds__(256) void phaseA_kernel(const float* __restrict__ x,
                                                     const float* __restrict__ w_a,
                                                     float* __restrict__ out) {
    int tid = threadIdx.x;

    // zero this block's slice of out (8M floats / 1024 blocks), BEFORE early return
    {
        int bid = blockIdx.x + (NEXP * TPE) * (blockIdx.y + 2 * blockIdx.z);  // 0..1023
        float4* oz = (float4*)out + (size_t)bid * 2048;
        float4 z = make_float4(0.f, 0.f, 0.f, 0.f);
#pragma unroll
        for (int i = 0; i < 8; i++) oz[i * 256 + tid] = z;
    }

    int k  = blockIdx.y;
    int ti = blockIdx.x;
    int e   = ti >> 2;             // expert
    int sub = ti & 3;              // tile slot within expert
    int cnt = d_run[k * 16 + e];
    int t0i = sub * TILE_T;
    int cl  = cnt - t0i;
    if (cl <= 0) return;
    if (cl > TILE_T) cl = TILE_T;
    int start = e * NTOK + t0i;
    int ds = blockIdx.z;

    extern __shared__ float dyn[];           // 2 x (sx[128*68] + sw[16*68])
    __shared__ int s_tok[128];

    int j2  = tid >> 1;        // token slot
    int rh  = tid & 1;         // rank parity: handles ranks {2i+rh}

    if (tid < 128) {
        int jcl = tid < cl ? tid : (cl - 1);
        s_tok[tid] = d_list[k][start + jcl];
    }
    __syncthreads();

    const float* wa_e = w_a + (size_t)e * RANK * DIN;
    int dbase0 = ds * (DIN / DSPLIT);        // 256-wide slice, 4 chunks of 64

    auto stage = [&](int buf, int ch) {
        float* sxb = dyn + buf * A_BUF_FLOATS;
        float* swb = sxb + 128 * 68;
        int db = dbase0 + ch * 64;
#pragma unroll
        for (int it = 0; it < 8; it++) {
            int l = it * 256 + tid;
            int tok = l >> 4, c4 = l & 15;
            cp16(sxb + tok * 68 + c4 * 4,
                 x + (size_t)s_tok[tok] * DIN + db + c4 * 4);
        }
        {
            int r = tid >> 4, c4 = tid & 15;
            cp16(swb + r * 68 + c4 * 4,
                 wa_e + (size_t)r * DIN + db + c4 * 4);
        }
        CP_COMMIT();
    };

    ull acc[8];
#pragma unroll
    for (int i = 0; i < 8; i++) acc[i] = 0ull;

    stage(0, 0);
    int buf = 0;
#pragma unroll
    for (int ch = 0; ch < 4; ch++) {
        if (ch < 3) { stage(buf ^ 1, ch + 1); CP_WAIT(1); }
        else        { CP_WAIT(0); }
        __syncthreads();

        const float* sxb = dyn + buf * A_BUF_FLOATS;
        const float* swb = sxb + 128 * 68;
        const float* sxr = sxb + j2 * 68;
        const float* swr = swb + rh * 68;    // rank 2i+rh at row offset (2i+rh)*68
#pragma unroll
        for (int c4 = 0; c4 < 16; c4++) {
            ulonglong2 xv = *(const ulonglong2*)(sxr + c4 * 4);
#pragma unroll
            for (int i = 0; i < 8; i++) {
                ulonglong2 wv = *(const ulonglong2*)(swr + (2 * i) * 68 + c4 * 4);
                fma2(acc[i], xv.x, wv.x);
                fma2(acc[i], xv.y, wv.y);
            }
        }
        __syncthreads();
        buf ^= 1;
    }

    if (j2 < cl) {
        int a = s_tok[j2] * 2 + k;
        float* p = &d_part[ds][(size_t)a * RANK];
#pragma unroll
        for (int i = 0; i < 8; i++) p[2 * i + rh] = hadd2(acc[i]);
    }
}

// ---------------- kernel 3: phase B — 2 consecutive d/thread, 256 threads, red_v2 (frozen) ----------------
// grid (NEXP*TPE, DOUT/512, 4), block 256. z = (zslice<<1)|k.
__global__ __launch_bounds__(256) void phaseB_kernel(const float* __restrict__ w_b,
                                                     const float* __restrict__ routing,
                                                     float* __restrict__ out) {
    int kk = blockIdx.z & 1;
    int zs = blockIdx.z >> 1;
    int ti = blockIdx.x;
    int e   = ti >> 2;
    int sub = ti & 3;
    int cnt = d_run[kk * 16 + e];
    int t0i = sub * TILE_T + zs * WIN;
    int cl  = cnt - t0i;
    if (cl <= 0) return;
    if (cl > WIN) cl = WIN;
    int start = e * NTOK + t0i;

    __shared__ float sg[WIN * 16];
    __shared__ int   s_tok[WIN];

    int tid = threadIdx.x;
    if (tid < WIN) {
        int jcl = tid < cl ? tid : (cl - 1);
        s_tok[tid] = d_list[kk][start + jcl];
    }
    {   // stage g with fused DSPLIT-combine + silu*routing*alpha: 64 tok x 4 quads
        int j = tid >> 2, q = tid & 3;
        int jcl = j < cl ? j : (cl - 1);
        int t = d_list[kk][start + jcl];
        int a = t * 2 + kk;
        size_t off = (size_t)a * RANK + q * 4;
        float4 s = *(const float4*)(&d_part[0][off]);
#pragma unroll
        for (int ds = 1; ds < DSPLIT; ds++) {
            float4 p = *(const float4*)(&d_part[ds][off]);
            s.x += p.x; s.y += p.y; s.z += p.z; s.w += p.w;
        }
        float rs = routing[a] * ALPHA;
        float4 g;
        g.x = rs * s.x * (1.0f / (1.0f + __expf(-s.x)));
        g.y = rs * s.y * (1.0f / (1.0f + __expf(-s.y)));
        g.z = rs * s.z * (1.0f / (1.0f + __expf(-s.z)));
        g.w = rs * s.w * (1.0f / (1.0f + __expf(-s.w)));
        *(float4*)(sg + j * 16 + q * 4) = g;
    }
    __syncthreads();

    int d0 = blockIdx.y * 512 + tid * 2;     // 2 consecutive outputs per thread
    const ulonglong2* wbp0 = (const ulonglong2*)(w_b + ((size_t)e * DOUT + d0) * RANK);
    const ulonglong2* wbp1 = (const ulonglong2*)(w_b + ((size_t)e * DOUT + d0 + 1) * RANK);
    ulonglong2 p0 = wbp0[0], p1 = wbp0[1], p2 = wbp0[2], p3 = wbp0[3];
    ulonglong2 q0 = wbp1[0], q1 = wbp1[1], q2 = wbp1[2], q3 = wbp1[3];

    for (int j0 = 0; j0 < cl; j0 += GRP) {
        float r0[GRP], r1[GRP];
#pragma unroll
        for (int u = 0; u < GRP; u++) {
            int jj = j0 + u; if (jj >= cl) jj = cl - 1;
            const ulonglong2* g = (const ulonglong2*)(sg + jj * 16);
            ulonglong2 ga = g[0], gb = g[1], gc = g[2], gd = g[3];
            ull a0 = 0ull, a1 = 0ull, b0 = 0ull, b1 = 0ull;
            fma2(a0, ga.x, p0.x); fma2(a1, ga.y, p0.y);
            fma2(b0, ga.x, q0.x); fma2(b1, ga.y, q0.y);
            fma2(a0, gb.x, p1.x); fma2(a1, gb.y, p1.y);
            fma2(b0, gb.x, q1.x); fma2(b1, gb.y, q1.y);
            fma2(a0, gc.x, p2.x); fma2(a1, gc.y, p2.y);
            fma2(b0, gc.x, q2.x); fma2(b1, gc.y, q2.y);
            fma2(a0, gd.x, p3.x); fma2(a1, gd.y, p3.y);
            fma2(b0, gd.x, q3.x); fma2(b1, gd.y, q3.y);
            r0[u] = hadd2(add2(a0, a1));
            r1[u] = hadd2(add2(b0, b1));
        }
#pragma unroll
        for (int u = 0; u < GRP; u++) {
            int jj = j0 + u;
            if (jj < cl) {
                red_v2(out + (size_t)s_tok[jj] * DOUT + d0, r0[u], r1[u]);
            }
        }
    }
}

// ---------------- kernel 4: zero d_run for the NEXT call (replaces front memset node) ----------------
__global__ void zero_run_kernel() {
    if (threadIdx.x < 32) d_run[threadIdx.x] = 0;
}

// ---------------- launcher ----------------
extern "C" void kernel_launch(void* const* d_in, const int* in_sizes, int n_in,
                              void* d_out, int out_size) {
    const float* x       = (const float*)d_in[0];
    const float* routing = (const float*)d_in[1];
    const int*   idxs    = (const int*)d_in[2];   // int32 (JAX x64 disabled)
    const float* w_a     = (const float*)d_in[3];
    const float* w_b     = (const float*)d_in[4];
    float*       out     = (float*)d_out;

    cudaFuncSetAttribute(phaseA_kernel, cudaFuncAttributeMaxDynamicSharedMemorySize,
                         A_SMEM_BYTES);

    // d_run is zero on entry: static zero-init on first call, zero_run_kernel thereafter.
    scatter_kernel<<<NASSIGN / 256, 256>>>(idxs);
    phaseA_kernel<<<dim3(NEXP * TPE, 2, DSPLIT), 256, A_SMEM_BYTES>>>(x, w_a, out);
    phaseB_kernel<<<dim3(NEXP * TPE, DOUT / 512, 4), 256>>>(w_b, routing, out);
    zero_run_kernel<<<1, 32>>>();   // also shifts ncu -s 5 onto phaseA (launch #5)
}